// round 1
// baseline (speedup 1.0000x reference)
#include <cuda_runtime.h>
#include <cstdint>

// ---------------------------------------------------------------------------
// PairwiseMLPLinkPredictor: fused gather + elemwise product + 3-layer MLP.
//   feats = x[a] * x[b]            [E, 256]
//   h1 = relu(feats @ W1 + b1)     [E, 256]
//   h2 = relu(h1 @ W2 + b2)        [E, 128]
//   out = h2 @ W3 + b3             [E]
// Baseline: fp32 with packed fma.rn.f32x2 (FFMA2) -> 128 MAC/cyc/SM.
// ---------------------------------------------------------------------------

#define TILE_E   64
#define NTH      256
#define DD       256
#define HH       256
#define HALF_H   128

#define SA_STRIDE 260              // feats smem row stride (pad 4 -> conflict-free, 16B aligned)
#define SB_STRIDE 65               // h1-transposed smem col stride (pad 1 -> conflict-free)
#define SA_FLOATS (64 * 260)       // 16640 floats; note 256*65 == 16640 too (sB reuses sA)
#define SW_FLOATS (64 * 256)       // weight k-slice staging
#define SMEM_FLOATS (SA_FLOATS + SW_FLOATS)
#define SMEM_BYTES  (SMEM_FLOATS * 4 + 128 * 8)   // + 128 int64 pair indices = 133120 B

typedef unsigned long long u64;

__device__ __forceinline__ u64 pack2(float lo, float hi) {
    u64 r;
    asm("mov.b64 %0, {%1, %2};" : "=l"(r) : "f"(lo), "f"(hi));
    return r;
}
__device__ __forceinline__ void unpack2(u64 v, float& lo, float& hi) {
    asm("mov.b64 {%0, %1}, %2;" : "=f"(lo), "=f"(hi) : "l"(v));
}
// Packed dual-FMA: d.lo += a.lo*b.lo; d.hi += a.hi*b.hi  (FFMA2 in SASS)
__device__ __forceinline__ void ffma2(u64& d, u64 a, u64 b) {
    asm("fma.rn.f32x2 %0, %1, %2, %0;" : "+l"(d) : "l"(a), "l"(b));
}

__global__ void __launch_bounds__(NTH, 1)
pairmlp_kernel(const float* __restrict__ x,
               const float* __restrict__ W1, const float* __restrict__ b1,
               const float* __restrict__ W2, const float* __restrict__ b2,
               const float* __restrict__ W3, const float* __restrict__ b3,
               const void*  __restrict__ ep,   // edge_pairs: int32 or int64 (probed)
               float* __restrict__ out, int E)
{
    extern __shared__ float smem[];
    float*     sA   = smem;                       // feats [64][260]  /  later h1^T [256][65]
    float*     sW   = smem + SA_FLOATS;           // weight slice [64][256] (or [64][128])
    long long* sIdx = (long long*)(smem + SMEM_FLOATS);   // 128 pair indices

    const int tid = threadIdx.x;
    const long long e0 = (long long)blockIdx.x * TILE_E;

    // ---- dtype probe: int64 edge_pairs -> odd int32 words of first 1KB are all 0 ----
    int probe = 0;
    if (tid < 128) probe = ((const int*)ep)[2 * tid + 1];
    const bool is32 = (__syncthreads_or(probe != 0) != 0);

    // ---- load this block's 64 pair indices ----
    if (tid < 128) {
        long long gi = 2 * e0 + tid;
        long long v;
        if (gi < 2LL * E) {
            v = is32 ? (long long)((const int*)ep)[gi]
                     : ((const long long*)ep)[gi];
        } else {
            v = 0;
        }
        sIdx[tid] = v;
    }
    __syncthreads();

    // ---- stage feats[p][k] = x[a][k] * x[b][k] into sA ----
    {
        const int p  = tid >> 2;
        const int kq = tid & 3;
        const float* xa = x + (size_t)sIdx[2 * p]     * DD;
        const float* xb = x + (size_t)sIdx[2 * p + 1] * DD;
        float* dst = sA + p * SA_STRIDE;
        #pragma unroll
        for (int i = 0; i < 16; i++) {
            const int k = kq * 64 + i * 4;
            float4 a = *(const float4*)(xa + k);
            float4 b = *(const float4*)(xb + k);
            float4 f;
            f.x = a.x * b.x; f.y = a.y * b.y; f.z = a.z * b.z; f.w = a.w * b.w;
            *(float4*)(dst + k) = f;
        }
    }

    const int ty = tid >> 4;        // 0..15 -> 4 pairs each
    const int tx = tid & 15;        // 0..15 -> 16 outs each (layer1)
    const int p0 = ty * 4;

    // =====================  layer 1: h1 = relu(feats @ W1 + b1)  =====================
    // thread micro-tile: pairs p0..p0+3  x  outs {tx*4 + oo*64 + j : oo<4, j<4}
    u64 acc1[4][8];
    #pragma unroll
    for (int i = 0; i < 4; i++)
        #pragma unroll
        for (int j = 0; j < 8; j++) acc1[i][j] = 0ull;

    #pragma unroll 1
    for (int ks = 0; ks < 4; ks++) {
        __syncthreads();                       // prior slice consumed (and feats ready at ks=0)
        #pragma unroll
        for (int j = 0; j < 16; j++) {         // stage W1 rows ks*64..+63 (64KB, coalesced)
            const int f4 = tid + j * 256;
            *(float4*)(sW + 4 * f4) = *(const float4*)(W1 + (size_t)ks * 16384 + 4 * f4);
        }
        __syncthreads();

        #pragma unroll 8
        for (int k = 0; k < 64; k++) {
            u64 ap[4];
            #pragma unroll
            for (int pp = 0; pp < 4; pp++) {
                const float a = sA[(p0 + pp) * SA_STRIDE + ks * 64 + k];
                ap[pp] = pack2(a, a);
            }
            const ulonglong2* wrow = (const ulonglong2*)(sW + k * 256);
            #pragma unroll
            for (int oo = 0; oo < 4; oo++) {
                const ulonglong2 wv = wrow[tx + oo * 16];     // 4 consecutive floats
                #pragma unroll
                for (int pp = 0; pp < 4; pp++) {
                    ffma2(acc1[pp][oo * 2 + 0], ap[pp], wv.x);
                    ffma2(acc1[pp][oo * 2 + 1], ap[pp], wv.y);
                }
            }
        }
    }

    // bias + relu, write h1 transposed into sB[o][p] (stride 65) reusing sA region
    __syncthreads();
    #pragma unroll
    for (int oo = 0; oo < 4; oo++) {
        #pragma unroll
        for (int h = 0; h < 2; h++) {
            const int ob = tx * 4 + oo * 64 + h * 2;
            const float bi0 = b1[ob], bi1 = b1[ob + 1];
            #pragma unroll
            for (int pp = 0; pp < 4; pp++) {
                float v0, v1;
                unpack2(acc1[pp][oo * 2 + h], v0, v1);
                v0 = fmaxf(v0 + bi0, 0.0f);
                v1 = fmaxf(v1 + bi1, 0.0f);
                sA[(ob + 0) * SB_STRIDE + p0 + pp] = v0;
                sA[(ob + 1) * SB_STRIDE + p0 + pp] = v1;
            }
        }
    }

    // =====================  layer 2: h2 = relu(h1 @ W2 + b2)  =====================
    // thread micro-tile: pairs p0..p0+3  x  outs {tx*4 + oo*64 + j : oo<2, j<4}
    u64 acc2[4][4];
    #pragma unroll
    for (int i = 0; i < 4; i++)
        #pragma unroll
        for (int j = 0; j < 4; j++) acc2[i][j] = 0ull;

    #pragma unroll 1
    for (int ks = 0; ks < 4; ks++) {
        __syncthreads();                       // sB writes done / prior W2 slice consumed
        #pragma unroll
        for (int j = 0; j < 8; j++) {          // stage W2 rows ks*64..+63 (32KB)
            const int f4 = tid + j * 256;
            *(float4*)(sW + 4 * f4) = *(const float4*)(W2 + (size_t)ks * 8192 + 4 * f4);
        }
        __syncthreads();

        #pragma unroll 8
        for (int k = 0; k < 64; k++) {
            u64 ap[4];
            #pragma unroll
            for (int pp = 0; pp < 4; pp++) {
                const float a = sA[(ks * 64 + k) * SB_STRIDE + p0 + pp];
                ap[pp] = pack2(a, a);
            }
            const ulonglong2* wrow = (const ulonglong2*)(sW + k * 128);
            #pragma unroll
            for (int oo = 0; oo < 2; oo++) {
                const ulonglong2 wv = wrow[tx + oo * 16];
                #pragma unroll
                for (int pp = 0; pp < 4; pp++) {
                    ffma2(acc2[pp][oo * 2 + 0], ap[pp], wv.x);
                    ffma2(acc2[pp][oo * 2 + 1], ap[pp], wv.y);
                }
            }
        }
    }

    // =====================  layer 3: out = h2 @ W3 + b3  =====================
    float part[4] = {0.f, 0.f, 0.f, 0.f};
    #pragma unroll
    for (int oo = 0; oo < 2; oo++) {
        #pragma unroll
        for (int h = 0; h < 2; h++) {
            const int ob = tx * 4 + oo * 64 + h * 2;
            const float bi0 = b2[ob], bi1 = b2[ob + 1];
            const float w0 = W3[ob], w1 = W3[ob + 1];
            #pragma unroll
            for (int pp = 0; pp < 4; pp++) {
                float v0, v1;
                unpack2(acc2[pp][oo * 2 + h], v0, v1);
                v0 = fmaxf(v0 + bi0, 0.0f);
                v1 = fmaxf(v1 + bi1, 0.0f);
                part[pp] += v0 * w0 + v1 * w1;
            }
        }
    }
    // reduce across the 16 tx lanes (each half-warp is one ty group)
    #pragma unroll
    for (int s = 8; s >= 1; s >>= 1)
        #pragma unroll
        for (int pp = 0; pp < 4; pp++)
            part[pp] += __shfl_down_sync(0xffffffffu, part[pp], s, 16);

    if (tx == 0) {
        const float bb = b3[0];
        #pragma unroll
        for (int pp = 0; pp < 4; pp++) {
            const long long e = e0 + p0 + pp;
            if (e < E) out[e] = part[pp] + bb;
        }
    }
}

extern "C" void kernel_launch(void* const* d_in, const int* in_sizes, int n_in,
                              void* d_out, int out_size)
{
    const float* x  = (const float*)d_in[0];
    const float* W1 = (const float*)d_in[1];
    const float* b1 = (const float*)d_in[2];
    const float* W2 = (const float*)d_in[3];
    const float* b2 = (const float*)d_in[4];
    const float* W3 = (const float*)d_in[5];
    const float* b3 = (const float*)d_in[6];
    // d_in[7] = edge_index (unused by the reference computation)
    const void*  ep = d_in[8];
    float* out = (float*)d_out;

    const int E = out_size;
    const int nblocks = (E + TILE_E - 1) / TILE_E;

    cudaFuncSetAttribute(pairmlp_kernel,
                         cudaFuncAttributeMaxDynamicSharedMemorySize, SMEM_BYTES);
    pairmlp_kernel<<<nblocks, NTH, SMEM_BYTES>>>(x, W1, b1, W2, b2, W3, b3, ep, out, E);
}

// round 4
// speedup vs baseline: 2.8945x; 2.8945x over previous
#include <cuda_runtime.h>
#include <cuda_fp16.h>
#include <cstdint>

// ============================================================================
// PairwiseMLPLinkPredictor — fp16 warp-MMA (mma.sync m16n8k16, HMMA path).
// tcgen05 is unavailable: harness PTX target is sm_103 (no 'a' feature set).
//   feats = fp16(x[a] * x[b])        [128 pairs/CTA, K=256] -> SMEM (swizzled)
//   h1 = fp16(relu(feats @ W1 + b1)) -> SMEM (overwrites feats)
//   D2 = h1 @ W2 ; out = relu(D2+b2).W3 + b3  (fp32 epilogue from accum regs)
// W1/W2 pre-transposed([N][K]) + fp16 + pre-swizzled by prep kernel; CTAs pull
// the ready-made SMEM image with cp.async (overlapped with gather / epilogue1).
// ============================================================================

#define NTH    512
#define TILE_M 128

// ---- SMEM layout (bytes) ----
#define OFF_FEATS 0         // 65536 : feats / h1  [128][256] f16, 16B-chunk swizzle
#define OFF_W     65536     // 131072: W1^T image (W2^T overlays first 65536)
#define OFF_IDX   196608    // 2048  : 256 x int64 pair indices
#define OFF_B1    198656    // 1024
#define OFF_B2    199680    // 512
#define OFF_W3    200192    // 512
#define OFF_PART  200704    // 2048  : layer-3 partials [4][128]
#define SMEM_BYTES 202752

// swizzled byte offset inside a [rows][256] fp16 tile (row stride 512B):
// 16B chunk index c = k>>3 is XORed with (row&7)  -> conflict-free ldmatrix.
__host__ __device__ __forceinline__ uint32_t timg(int r, int k) {
    return (uint32_t)(r * 512 + ((((k >> 3) ^ (r & 7)) & 31) << 4) + ((k & 7) << 1));
}

// ---- global fp16 weight images (prep kernel output, smem-verbatim) ----
__device__ __align__(1024) unsigned char g_W1h[131072];  // [256][256] f16 swizzled
__device__ __align__(1024) unsigned char g_W2h[65536];   // [128][256] f16 swizzled

// ---------------------------------------------------------------------------
__device__ __forceinline__ uint32_t smem_u32(const void* p) {
    uint32_t a;
    asm("{ .reg .u64 t; cvta.to.shared.u64 t, %1; cvt.u32.u64 %0, t; }" : "=r"(a) : "l"(p));
    return a;
}
__device__ __forceinline__ void ldsm_x4(uint32_t r[4], uint32_t addr) {
    asm volatile("ldmatrix.sync.aligned.m8n8.x4.shared.b16 {%0,%1,%2,%3}, [%4];"
                 : "=r"(r[0]), "=r"(r[1]), "=r"(r[2]), "=r"(r[3]) : "r"(addr));
}
__device__ __forceinline__ void mma16816(float c[4], const uint32_t a[4], const uint32_t b0, const uint32_t b1) {
    asm volatile("mma.sync.aligned.m16n8k16.row.col.f32.f16.f16.f32 "
                 "{%0,%1,%2,%3}, {%4,%5,%6,%7}, {%8,%9}, {%0,%1,%2,%3};"
                 : "+f"(c[0]), "+f"(c[1]), "+f"(c[2]), "+f"(c[3])
                 : "r"(a[0]), "r"(a[1]), "r"(a[2]), "r"(a[3]), "r"(b0), "r"(b1));
}
#define CP16(dst, src) \
    asm volatile("cp.async.cg.shared.global [%0], [%1], 16;" :: "r"(dst), "l"(src) : "memory")
#define CP_COMMIT() asm volatile("cp.async.commit_group;" ::: "memory")
#define CP_WAIT0()  asm volatile("cp.async.wait_group 0;" ::: "memory")

// ---------------------------------------------------------------------------
// Prep: W1h[n][k] = fp16(W1[k*256+n]) swizzled; W2h[n][k] = fp16(W2[k*128+n]).
// ---------------------------------------------------------------------------
__global__ void prep_kernel(const float* __restrict__ W1, const float* __restrict__ W2) {
    const int i = blockIdx.x * blockDim.x + threadIdx.x;  // 65536
    {
        const int n = i >> 8, k = i & 255;
        *(__half*)(g_W1h + timg(n, k)) = __float2half(W1[k * 256 + n]);
    }
    if (i < 32768) {
        const int n = i >> 8, k = i & 255;
        *(__half*)(g_W2h + timg(n, k)) = __float2half(W2[k * 128 + n]);
    }
}

// ---------------------------------------------------------------------------
__global__ void __launch_bounds__(NTH, 1)
pairmlp_hmma_kernel(const float* __restrict__ x,
                    const float* __restrict__ b1, const float* __restrict__ b2,
                    const float* __restrict__ W3, const float* __restrict__ b3,
                    const void*  __restrict__ ep, float* __restrict__ out, int E)
{
    extern __shared__ char smem[];
    const uint32_t sb = smem_u32(smem);
    const int tid = threadIdx.x, w = tid >> 5, lane = tid & 31;
    const int g = lane >> 2, tig = lane & 3;
    const long long e0 = (long long)blockIdx.x * TILE_M;

    long long* sIdx = (long long*)(smem + OFF_IDX);
    float* sB1 = (float*)(smem + OFF_B1);
    float* sB2 = (float*)(smem + OFF_B2);
    float* sW3 = (float*)(smem + OFF_W3);
    float* sPart = (float*)(smem + OFF_PART);

    // ---- dtype probe: int64 edge_pairs -> odd int32 words of first 1KB all 0 ----
    int probe = 0;
    if (tid < 128) probe = ((const int*)ep)[2 * tid + 1];
    const bool is32 = (__syncthreads_or(probe != 0) != 0);

    // ---- kick W1 image copy (128KB) via cp.async, overlap with gather ----
    #pragma unroll
    for (int i = 0; i < 16; i++) {
        const int c = tid + i * NTH;                // 8192 chunks of 16B
        CP16(sb + OFF_W + c * 16, g_W1h + c * 16);
    }
    CP_COMMIT();

    // ---- indices + small vectors ----
    if (tid < 256) {
        long long gi = 2 * e0 + tid, v = 0;
        if (gi < 2LL * E) v = is32 ? (long long)((const int*)ep)[gi] : ((const long long*)ep)[gi];
        sIdx[tid] = v;
    }
    if (tid < 256) sB1[tid] = b1[tid];
    if (tid >= 256 && tid < 384) { sB2[tid - 256] = b2[tid - 256]; sW3[tid - 256] = W3[tid - 256]; }
    __syncthreads();

    // ---- gather + product -> fp16 feats (swizzled image) ----
    {
        const int p = tid >> 2, q = tid & 3;
        const float* xa = x + (size_t)sIdx[2 * p] * 256;
        const float* xb = x + (size_t)sIdx[2 * p + 1] * 256;
        #pragma unroll
        for (int j = 0; j < 8; j++) {
            const int k0 = q * 64 + j * 8;
            float4 a0 = __ldg((const float4*)(xa + k0));
            float4 a1 = __ldg((const float4*)(xa + k0 + 4));
            float4 c0 = __ldg((const float4*)(xb + k0));
            float4 c1 = __ldg((const float4*)(xb + k0 + 4));
            union { __half2 h; uint32_t u; } p0, p1, p2, p3;
            p0.h = __floats2half2_rn(a0.x * c0.x, a0.y * c0.y);
            p1.h = __floats2half2_rn(a0.z * c0.z, a0.w * c0.w);
            p2.h = __floats2half2_rn(a1.x * c1.x, a1.y * c1.y);
            p3.h = __floats2half2_rn(a1.z * c1.z, a1.w * c1.w);
            *(uint4*)(smem + OFF_FEATS + timg(p, k0)) = make_uint4(p0.u, p1.u, p2.u, p3.u);
        }
    }
    CP_WAIT0();
    __syncthreads();

    // ================= layer 1: 128x256x256, warp tile 32x64 =================
    const int wm = w & 3, wn = w >> 2;              // 4 M-groups x 4 N-groups
    float acc[2][8][4];
    #pragma unroll
    for (int mi = 0; mi < 2; mi++)
        #pragma unroll
        for (int ni = 0; ni < 8; ni++)
            #pragma unroll
            for (int v = 0; v < 4; v++) acc[mi][ni][v] = 0.0f;

    // per-thread ldmatrix row geometry
    const int arow0 = wm * 32 + ((lane >> 3) & 1) * 8 + (lane & 7);   // + mi*16
    const int acsel = lane >> 4;                                       // k half
    const int brow0 = ((lane >> 4) & 1) * 8 + (lane & 7);              // + n0
    const int bcsel = (lane >> 3) & 1;                                 // k half

    {
        const uint32_t aBase = sb + OFF_FEATS;
        const uint32_t bBase = sb + OFF_W;
        #pragma unroll
        for (int ks = 0; ks < 16; ks++) {
            uint32_t af[2][4];
            #pragma unroll
            for (int mi = 0; mi < 2; mi++) {
                const int r = arow0 + mi * 16;
                ldsm_x4(af[mi], aBase + r * 512 + ((((2 * ks + acsel) ^ (r & 7)) & 31) << 4));
            }
            #pragma unroll
            for (int nb = 0; nb < 4; nb++) {
                const int r = wn * 64 + nb * 16 + brow0;
                uint32_t bf[4];
                ldsm_x4(bf, bBase + r * 512 + ((((2 * ks + bcsel) ^ (r & 7)) & 31) << 4));
                #pragma unroll
                for (int mi = 0; mi < 2; mi++) {
                    mma16816(acc[mi][nb * 2 + 0], af[mi], bf[0], bf[1]);
                    mma16816(acc[mi][nb * 2 + 1], af[mi], bf[2], bf[3]);
                }
            }
        }
    }

    __syncthreads();   // everyone done reading feats + W1

    // ---- kick W2 image copy (64KB) over the W1 region; overlap epilogue1 ----
    #pragma unroll
    for (int i = 0; i < 8; i++) {
        const int c = tid + i * NTH;                // 4096 chunks
        CP16(sb + OFF_W + c * 16, g_W2h + c * 16);
    }
    CP_COMMIT();

    // ---- epilogue 1: h1 = fp16(relu(acc + b1)) -> feats image ----
    #pragma unroll
    for (int mi = 0; mi < 2; mi++) {
        const int r0 = wm * 32 + mi * 16 + g, r1 = r0 + 8;
        #pragma unroll
        for (int ni = 0; ni < 8; ni++) {
            const int c0 = wn * 64 + ni * 8 + 2 * tig;
            const float2 bb = *(const float2*)&sB1[c0];
            union { __half2 h; uint32_t u; } lo, hi;
            lo.h = __floats2half2_rn(fmaxf(acc[mi][ni][0] + bb.x, 0.0f),
                                     fmaxf(acc[mi][ni][1] + bb.y, 0.0f));
            hi.h = __floats2half2_rn(fmaxf(acc[mi][ni][2] + bb.x, 0.0f),
                                     fmaxf(acc[mi][ni][3] + bb.y, 0.0f));
            *(uint32_t*)(smem + OFF_FEATS + timg(r0, c0)) = lo.u;
            *(uint32_t*)(smem + OFF_FEATS + timg(r1, c0)) = hi.u;
        }
    }
    CP_WAIT0();
    __syncthreads();

    // ================= layer 2: 128x128x256, warp tile 32x32 =================
    float ac2[2][4][4];
    #pragma unroll
    for (int mi = 0; mi < 2; mi++)
        #pragma unroll
        for (int ni = 0; ni < 4; ni++)
            #pragma unroll
            for (int v = 0; v < 4; v++) ac2[mi][ni][v] = 0.0f;

    {
        const uint32_t aBase = sb + OFF_FEATS;
        const uint32_t bBase = sb + OFF_W;
        #pragma unroll
        for (int ks = 0; ks < 16; ks++) {
            uint32_t af[2][4];
            #pragma unroll
            for (int mi = 0; mi < 2; mi++) {
                const int r = arow0 + mi * 16;
                ldsm_x4(af[mi], aBase + r * 512 + ((((2 * ks + acsel) ^ (r & 7)) & 31) << 4));
            }
            #pragma unroll
            for (int nb = 0; nb < 2; nb++) {
                const int r = wn * 32 + nb * 16 + brow0;
                uint32_t bf[4];
                ldsm_x4(bf, bBase + r * 512 + ((((2 * ks + bcsel) ^ (r & 7)) & 31) << 4));
                #pragma unroll
                for (int mi = 0; mi < 2; mi++) {
                    mma16816(ac2[mi][nb * 2 + 0], af[mi], bf[0], bf[1]);
                    mma16816(ac2[mi][nb * 2 + 1], af[mi], bf[2], bf[3]);
                }
            }
        }
    }

    // ---- layer 3: out = relu(D2 + b2) . W3 + b3 (fp32) ----
    #pragma unroll
    for (int mi = 0; mi < 2; mi++) {
        float s0 = 0.0f, s1 = 0.0f;
        #pragma unroll
        for (int ni = 0; ni < 4; ni++) {
            const int c0 = wn * 32 + ni * 8 + 2 * tig;
            const float2 bb = *(const float2*)&sB2[c0];
            const float2 ww = *(const float2*)&sW3[c0];
            s0 += fmaxf(ac2[mi][ni][0] + bb.x, 0.0f) * ww.x
                + fmaxf(ac2[mi][ni][1] + bb.y, 0.0f) * ww.y;
            s1 += fmaxf(ac2[mi][ni][2] + bb.x, 0.0f) * ww.x
                + fmaxf(ac2[mi][ni][3] + bb.y, 0.0f) * ww.y;
        }
        s0 += __shfl_xor_sync(0xffffffffu, s0, 1);
        s0 += __shfl_xor_sync(0xffffffffu, s0, 2);
        s1 += __shfl_xor_sync(0xffffffffu, s1, 1);
        s1 += __shfl_xor_sync(0xffffffffu, s1, 2);
        if (tig == 0) {
            const int r0 = wm * 32 + mi * 16 + g;
            sPart[wn * 128 + r0] = s0;
            sPart[wn * 128 + r0 + 8] = s1;
        }
    }
    __syncthreads();

    if (tid < 128) {
        const long long e = e0 + tid;
        if (e < E)
            out[e] = sPart[tid] + sPart[128 + tid] + sPart[256 + tid] + sPart[384 + tid]
                   + __ldg(b3);
    }
}

// ---------------------------------------------------------------------------
extern "C" void kernel_launch(void* const* d_in, const int* in_sizes, int n_in,
                              void* d_out, int out_size)
{
    const float* x  = (const float*)d_in[0];
    const float* W1 = (const float*)d_in[1];
    const float* b1 = (const float*)d_in[2];
    const float* W2 = (const float*)d_in[3];
    const float* b2 = (const float*)d_in[4];
    const float* W3 = (const float*)d_in[5];
    const float* b3 = (const float*)d_in[6];
    // d_in[7] = edge_index (unused)
    const void*  ep = d_in[8];
    float* out = (float*)d_out;

    const int E = out_size;
    prep_kernel<<<256, 256>>>(W1, W2);

    cudaFuncSetAttribute(pairmlp_hmma_kernel,
                         cudaFuncAttributeMaxDynamicSharedMemorySize, SMEM_BYTES);
    const int nblocks = (E + TILE_M - 1) / TILE_M;
    pairmlp_hmma_kernel<<<nblocks, NTH, SMEM_BYTES>>>(x, b1, b2, W3, b3, ep, out, E);
}